// round 4
// baseline (speedup 1.0000x reference)
#include <cuda_runtime.h>
#include <cuda_bf16.h>

// Problem dims
#define HB   1024            // hidden
#define NH   16
#define HD   64
#define SEQ  2048
#define BATCH 2
#define ROWS (BATCH*SEQ)     // 4096
#define EPS  1e-12f

// -------------------- scratch (device globals; no runtime allocs) -----------
__device__ float g_xn [ROWS*HB];   // layernorm output
__device__ float g_q  [ROWS*HB];   // [B,NH,S,HD]
__device__ float g_k  [ROWS*HB];
__device__ float g_v  [ROWS*HB];
__device__ float g_ctx[ROWS*HB];   // [B,S,H]

// ============================ LayerNorm =====================================
__global__ __launch_bounds__(256) void ln_kernel(
    const float* __restrict__ x,
    const float* __restrict__ gamma,
    const float* __restrict__ beta)
{
    int row = blockIdx.x;
    const float* xr = x + (size_t)row * HB;
    int tid = threadIdx.x;

    float4 v = *(const float4*)(xr + tid * 4);
    float s  = v.x + v.y + v.z + v.w;
    float ss = v.x*v.x + v.y*v.y + v.z*v.z + v.w*v.w;

    // warp reduce
    #pragma unroll
    for (int o = 16; o; o >>= 1) {
        s  += __shfl_xor_sync(0xffffffffu, s,  o);
        ss += __shfl_xor_sync(0xffffffffu, ss, o);
    }
    __shared__ float sh_s[8], sh_ss[8];
    int wid = tid >> 5, lid = tid & 31;
    if (lid == 0) { sh_s[wid] = s; sh_ss[wid] = ss; }
    __syncthreads();
    if (wid == 0) {
        float a = (lid < 8) ? sh_s[lid]  : 0.f;
        float b = (lid < 8) ? sh_ss[lid] : 0.f;
        #pragma unroll
        for (int o = 4; o; o >>= 1) {
            a += __shfl_xor_sync(0xffffffffu, a, o);
            b += __shfl_xor_sync(0xffffffffu, b, o);
        }
        if (lid == 0) { sh_s[0] = a; sh_ss[0] = b; }
    }
    __syncthreads();
    float mean = sh_s[0] * (1.0f / HB);
    float var  = sh_ss[0] * (1.0f / HB) - mean * mean;
    float rstd = rsqrtf(var + EPS);

    float4 g = *(const float4*)(gamma + tid * 4);
    float4 be = *(const float4*)(beta + tid * 4);
    float4 o;
    o.x = (v.x - mean) * rstd * g.x + be.x;
    o.y = (v.y - mean) * rstd * g.y + be.y;
    o.z = (v.z - mean) * rstd * g.z + be.z;
    o.w = (v.w - mean) * rstd * g.w + be.w;
    *(float4*)(g_xn + (size_t)row * HB + tid * 4) = o;
}

// ============================ QKV GEMM ======================================
// C[m,n] = sum_k X[m,k]*W[n,k] + b[n], scattered to [B,NH,S,HD]
// 128x128 block, BK=8, 256 threads, 8x8 per thread.
__global__ __launch_bounds__(256) void qkv_gemm(
    const float* __restrict__ wq, const float* __restrict__ bq,
    const float* __restrict__ wk, const float* __restrict__ bk,
    const float* __restrict__ wv, const float* __restrict__ bv)
{
    const float* W; const float* bias; float* O;
    if      (blockIdx.z == 0) { W = wq; bias = bq; O = g_q; }
    else if (blockIdx.z == 1) { W = wk; bias = bk; O = g_k; }
    else                      { W = wv; bias = bv; O = g_v; }

    __shared__ float As[8 * 132];
    __shared__ float Bs[8 * 132];

    int tid = threadIdx.x;
    int aRow = tid >> 1;
    int aK4  = (tid & 1) << 2;
    int tx = tid & 15, ty = tid >> 4;

    const float* Aptr = g_xn + (size_t)(blockIdx.y * 128 + aRow) * HB + aK4;
    const float* Bptr = W    + (size_t)(blockIdx.x * 128 + aRow) * HB + aK4;

    float acc[8][8];
    #pragma unroll
    for (int i = 0; i < 8; i++)
        #pragma unroll
        for (int j = 0; j < 8; j++) acc[i][j] = 0.f;

    for (int k0 = 0; k0 < HB; k0 += 8) {
        float4 av = *(const float4*)(Aptr + k0);
        float4 bv = *(const float4*)(Bptr + k0);
        As[(aK4+0)*132 + aRow] = av.x;
        As[(aK4+1)*132 + aRow] = av.y;
        As[(aK4+2)*132 + aRow] = av.z;
        As[(aK4+3)*132 + aRow] = av.w;
        Bs[(aK4+0)*132 + aRow] = bv.x;
        Bs[(aK4+1)*132 + aRow] = bv.y;
        Bs[(aK4+2)*132 + aRow] = bv.z;
        Bs[(aK4+3)*132 + aRow] = bv.w;
        __syncthreads();
        #pragma unroll
        for (int kk = 0; kk < 8; kk++) {
            float a[8], b[8];
            *(float4*)&a[0] = *(const float4*)&As[kk*132 + ty*8];
            *(float4*)&a[4] = *(const float4*)&As[kk*132 + ty*8 + 4];
            *(float4*)&b[0] = *(const float4*)&Bs[kk*132 + tx*8];
            *(float4*)&b[4] = *(const float4*)&Bs[kk*132 + tx*8 + 4];
            #pragma unroll
            for (int i = 0; i < 8; i++)
                #pragma unroll
                for (int j = 0; j < 8; j++)
                    acc[i][j] += a[i] * b[j];
        }
        __syncthreads();
    }

    // epilogue: + bias, scatter to [B*NH, S, HD]
    int n0 = blockIdx.x * 128 + tx * 8;
    int h  = n0 >> 6;
    int d  = n0 & 63;
    float bb[8];
    #pragma unroll
    for (int j = 0; j < 8; j++) bb[j] = bias[n0 + j];
    #pragma unroll
    for (int i = 0; i < 8; i++) {
        int m  = blockIdx.y * 128 + ty * 8 + i;
        int b_ = m >> 11;
        int s_ = m & 2047;
        float* dst = O + ((size_t)(b_ * NH + h) * SEQ + s_) * HD + d;
        float4 o0, o1;
        o0.x = acc[i][0] + bb[0]; o0.y = acc[i][1] + bb[1];
        o0.z = acc[i][2] + bb[2]; o0.w = acc[i][3] + bb[3];
        o1.x = acc[i][4] + bb[4]; o1.y = acc[i][5] + bb[5];
        o1.z = acc[i][6] + bb[6]; o1.w = acc[i][7] + bb[7];
        *(float4*)(dst)     = o0;
        *(float4*)(dst + 4) = o1;
    }
}

// ============================ Flash attention ===============================
// BM=128 queries, BN=64 keys, HD=64. 256 threads: 16x16 grid,
// score tile per thread 8 rows x 4 keys; output tile 8 rows x 4 dims.
#define QT_S 132
#define KT_S 68
#define VS_S 68
#define PS_S 68
#define ATTN_SMEM ((64*QT_S + 64*KT_S + 64*VS_S + 128*PS_S) * 4)

__global__ __launch_bounds__(256) void attn_kernel(
    const float* __restrict__ mask)
{
    extern __shared__ float sm[];
    float* Qt = sm;                       // [64][132] transposed Q
    float* Kt = Qt + 64 * QT_S;           // [64][68]  transposed K
    float* Vs = Kt + 64 * KT_S;           // [64][68]  V row-major
    float* Ps = Vs + 64 * VS_S;           // [128][68] probs

    int tid = threadIdx.x;
    int bh = blockIdx.y;
    int b  = bh >> 4;
    int h  = bh & 15;
    int q0 = blockIdx.x * 128;

    const float* Qb = g_q + (size_t)bh * SEQ * HD + (size_t)q0 * HD;
    const float* Kb = g_k + (size_t)bh * SEQ * HD;
    const float* Vb = g_v + (size_t)bh * SEQ * HD;
    const float* mrow = mask + (size_t)b * SEQ;

    // load Q tile transposed: Qt[d][r]
    for (int t = tid; t < 128 * 16; t += 256) {
        int r  = t >> 4;
        int d4 = (t & 15) << 2;
        float4 qv = *(const float4*)(Qb + r * HD + d4);
        Qt[(d4+0)*QT_S + r] = qv.x;
        Qt[(d4+1)*QT_S + r] = qv.y;
        Qt[(d4+2)*QT_S + r] = qv.z;
        Qt[(d4+3)*QT_S + r] = qv.w;
    }

    int tx = tid & 15, ty = tid >> 4;
    int r0 = ty * 8;       // query rows
    int c0 = tx * 4;       // key cols (scores) / dim cols (output)

    float m_i[8], l_i[8], acc[8][4];
    #pragma unroll
    for (int i = 0; i < 8; i++) {
        m_i[i] = -1e30f; l_i[i] = 0.f;
        acc[i][0] = acc[i][1] = acc[i][2] = acc[i][3] = 0.f;
    }
    __syncthreads();

    for (int kt = 0; kt < SEQ; kt += 64) {
        // load K (transposed) and V tiles
        for (int t = tid; t < 64 * 16; t += 256) {
            int r  = t >> 4;
            int d4 = (t & 15) << 2;
            float4 kv = *(const float4*)(Kb + (size_t)(kt + r) * HD + d4);
            Kt[(d4+0)*KT_S + r] = kv.x;
            Kt[(d4+1)*KT_S + r] = kv.y;
            Kt[(d4+2)*KT_S + r] = kv.z;
            Kt[(d4+3)*KT_S + r] = kv.w;
            float4 vv = *(const float4*)(Vb + (size_t)(kt + r) * HD + d4);
            *(float4*)&Vs[r * VS_S + d4] = vv;
        }
        __syncthreads();

        // scores: s[8][4]
        float s[8][4];
        #pragma unroll
        for (int i = 0; i < 8; i++)
            s[i][0] = s[i][1] = s[i][2] = s[i][3] = 0.f;

        #pragma unroll 8
        for (int d = 0; d < 64; d++) {
            float a[8];
            *(float4*)&a[0] = *(const float4*)&Qt[d*QT_S + r0];
            *(float4*)&a[4] = *(const float4*)&Qt[d*QT_S + r0 + 4];
            float4 kb = *(const float4*)&Kt[d*KT_S + c0];
            #pragma unroll
            for (int i = 0; i < 8; i++) {
                s[i][0] += a[i] * kb.x;
                s[i][1] += a[i] * kb.y;
                s[i][2] += a[i] * kb.z;
                s[i][3] += a[i] * kb.w;
            }
        }

        // scale + mask
        float mk0 = mrow[kt + c0 + 0], mk1 = mrow[kt + c0 + 1];
        float mk2 = mrow[kt + c0 + 2], mk3 = mrow[kt + c0 + 3];
        #pragma unroll
        for (int i = 0; i < 8; i++) {
            s[i][0] = s[i][0] * 0.125f + mk0;
            s[i][1] = s[i][1] * 0.125f + mk1;
            s[i][2] = s[i][2] * 0.125f + mk2;
            s[i][3] = s[i][3] * 0.125f + mk3;
        }

        // online softmax (reduce over the 16 threads sharing rows)
        #pragma unroll
        for (int i = 0; i < 8; i++) {
            float tm = fmaxf(fmaxf(s[i][0], s[i][1]), fmaxf(s[i][2], s[i][3]));
            #pragma unroll
            for (int o = 8; o; o >>= 1)
                tm = fmaxf(tm, __shfl_xor_sync(0xffffffffu, tm, o));
            float mn = fmaxf(m_i[i], tm);
            float al = __expf(m_i[i] - mn);
            float p0 = __expf(s[i][0] - mn);
            float p1 = __expf(s[i][1] - mn);
            float p2 = __expf(s[i][2] - mn);
            float p3 = __expf(s[i][3] - mn);
            float rs = p0 + p1 + p2 + p3;
            #pragma unroll
            for (int o = 8; o; o >>= 1)
                rs += __shfl_xor_sync(0xffffffffu, rs, o);
            l_i[i] = l_i[i] * al + rs;
            m_i[i] = mn;
            acc[i][0] *= al; acc[i][1] *= al; acc[i][2] *= al; acc[i][3] *= al;
            float4 pq = make_float4(p0, p1, p2, p3);
            *(float4*)&Ps[(r0 + i) * PS_S + c0] = pq;
        }
        __syncthreads();

        // PV: acc[i][j] += sum_k P[r0+i][k] * V[k][c0+j]
        #pragma unroll 4
        for (int k = 0; k < 64; k += 4) {
            float4 v0 = *(const float4*)&Vs[(k+0)*VS_S + c0];
            float4 v1 = *(const float4*)&Vs[(k+1)*VS_S + c0];
            float4 v2 = *(const float4*)&Vs[(k+2)*VS_S + c0];
            float4 v3 = *(const float4*)&Vs[(k+3)*VS_S + c0];
            #pragma unroll
            for (int i = 0; i < 8; i++) {
                float4 p = *(const float4*)&Ps[(r0 + i) * PS_S + k];
                acc[i][0] += p.x*v0.x + p.y*v1.x + p.z*v2.x + p.w*v3.x;
                acc[i][1] += p.x*v0.y + p.y*v1.y + p.z*v2.y + p.w*v3.y;
                acc[i][2] += p.x*v0.z + p.y*v1.z + p.z*v2.z + p.w*v3.z;
                acc[i][3] += p.x*v0.w + p.y*v1.w + p.z*v2.w + p.w*v3.w;
            }
        }
        __syncthreads();
    }

    // epilogue -> g_ctx [B,S,H]
    #pragma unroll
    for (int i = 0; i < 8; i++) {
        float inv = 1.0f / l_i[i];
        int srow = q0 + r0 + i;
        float* dst = g_ctx + ((size_t)(b * SEQ + srow) * HB) + h * HD + c0;
        float4 o;
        o.x = acc[i][0] * inv; o.y = acc[i][1] * inv;
        o.z = acc[i][2] * inv; o.w = acc[i][3] * inv;
        *(float4*)dst = o;
    }
}

// ============================ Output GEMM + residual ========================
__global__ __launch_bounds__(256) void out_gemm(
    const float* __restrict__ wo, const float* __restrict__ bo,
    const float* __restrict__ hs, float* __restrict__ out)
{
    __shared__ float As[8 * 132];
    __shared__ float Bs[8 * 132];

    int tid = threadIdx.x;
    int aRow = tid >> 1;
    int aK4  = (tid & 1) << 2;
    int tx = tid & 15, ty = tid >> 4;

    const float* Aptr = g_ctx + (size_t)(blockIdx.y * 128 + aRow) * HB + aK4;
    const float* Bptr = wo    + (size_t)(blockIdx.x * 128 + aRow) * HB + aK4;

    float acc[8][8];
    #pragma unroll
    for (int i = 0; i < 8; i++)
        #pragma unroll
        for (int j = 0; j < 8; j++) acc[i][j] = 0.f;

    for (int k0 = 0; k0 < HB; k0 += 8) {
        float4 av = *(const float4*)(Aptr + k0);
        float4 bv = *(const float4*)(Bptr + k0);
        As[(aK4+0)*132 + aRow] = av.x;
        As[(aK4+1)*132 + aRow] = av.y;
        As[(aK4+2)*132 + aRow] = av.z;
        As[(aK4+3)*132 + aRow] = av.w;
        Bs[(aK4+0)*132 + aRow] = bv.x;
        Bs[(aK4+1)*132 + aRow] = bv.y;
        Bs[(aK4+2)*132 + aRow] = bv.z;
        Bs[(aK4+3)*132 + aRow] = bv.w;
        __syncthreads();
        #pragma unroll
        for (int kk = 0; kk < 8; kk++) {
            float a[8], b[8];
            *(float4*)&a[0] = *(const float4*)&As[kk*132 + ty*8];
            *(float4*)&a[4] = *(const float4*)&As[kk*132 + ty*8 + 4];
            *(float4*)&b[0] = *(const float4*)&Bs[kk*132 + tx*8];
            *(float4*)&b[4] = *(const float4*)&Bs[kk*132 + tx*8 + 4];
            #pragma unroll
            for (int i = 0; i < 8; i++)
                #pragma unroll
                for (int j = 0; j < 8; j++)
                    acc[i][j] += a[i] * b[j];
        }
        __syncthreads();
    }

    int n0 = blockIdx.x * 128 + tx * 8;
    float bb[8];
    #pragma unroll
    for (int j = 0; j < 8; j++) bb[j] = bo[n0 + j];
    #pragma unroll
    for (int i = 0; i < 8; i++) {
        int m = blockIdx.y * 128 + ty * 8 + i;
        const float* hr = hs + (size_t)m * HB + n0;
        float* dst = out + (size_t)m * HB + n0;
        float4 r0v = *(const float4*)(hr);
        float4 r1v = *(const float4*)(hr + 4);
        float4 o0, o1;
        o0.x = acc[i][0] + bb[0] + r0v.x;
        o0.y = acc[i][1] + bb[1] + r0v.y;
        o0.z = acc[i][2] + bb[2] + r0v.z;
        o0.w = acc[i][3] + bb[3] + r0v.w;
        o1.x = acc[i][4] + bb[4] + r1v.x;
        o1.y = acc[i][5] + bb[5] + r1v.y;
        o1.z = acc[i][6] + bb[6] + r1v.z;
        o1.w = acc[i][7] + bb[7] + r1v.w;
        *(float4*)(dst)     = o0;
        *(float4*)(dst + 4) = o1;
    }
}

// ============================ launch ========================================
extern "C" void kernel_launch(void* const* d_in, const int* in_sizes, int n_in,
                              void* d_out, int out_size)
{
    const float* hs    = (const float*)d_in[0];
    const float* mask  = (const float*)d_in[1];
    const float* wq    = (const float*)d_in[2];
    const float* bq    = (const float*)d_in[3];
    const float* wk    = (const float*)d_in[4];
    const float* bk    = (const float*)d_in[5];
    const float* wv    = (const float*)d_in[6];
    const float* bv    = (const float*)d_in[7];
    const float* wo    = (const float*)d_in[8];
    const float* bo    = (const float*)d_in[9];
    const float* gamma = (const float*)d_in[10];
    const float* beta  = (const float*)d_in[11];
    float* out = (float*)d_out;

    cudaFuncSetAttribute(attn_kernel,
                         cudaFuncAttributeMaxDynamicSharedMemorySize, ATTN_SMEM);

    ln_kernel<<<ROWS, 256>>>(hs, gamma, beta);
    qkv_gemm<<<dim3(HB/128, ROWS/128, 3), 256>>>(wq, bq, wk, bk, wv, bv);
    attn_kernel<<<dim3(SEQ/128, BATCH*NH), 256, ATTN_SMEM>>>(mask);
    out_gemm<<<dim3(HB/128, ROWS/128), 256>>>(wo, bo, hs, out);
}

// round 10
// speedup vs baseline: 2.8128x; 2.8128x over previous
#include <cuda_runtime.h>
#include <cuda_bf16.h>

// Problem dims
#define HB    1024
#define NH    16
#define HD    64
#define SEQ   2048
#define BATCH 2
#define ROWS  (BATCH*SEQ)     // 4096
#define EPS   1e-12f

// -------------------- scratch (device globals; no runtime allocs) -----------
__device__ float g_xn [ROWS*HB];   // layernorm output
__device__ float g_q  [ROWS*HB];   // [B,NH,S,HD]
__device__ float g_k  [ROWS*HB];
__device__ float g_v  [ROWS*HB];
__device__ float g_ctx[ROWS*HB];   // [B,S,H]

// -------------------- bf16 mma helpers --------------------------------------
// pack2(a,b): a -> low 16 bits (lower k index), b -> high 16 bits
__device__ __forceinline__ unsigned pack2(float a, float b) {
    unsigned r;
    asm("{ .reg .b16 lo, hi;\n\t"
        "cvt.rn.bf16.f32 lo, %1;\n\t"
        "cvt.rn.bf16.f32 hi, %2;\n\t"
        "mov.b32 %0, {lo, hi}; }"
        : "=r"(r) : "f"(a), "f"(b));
    return r;
}
__device__ __forceinline__ void split1(float f, float& h, float& l) {
    float hf = __bfloat162float(__float2bfloat16_rn(f));
    h = hf;
    l = f - hf;
}
// D += A(16x16) * B(16x8), bf16 inputs, f32 accum.
__device__ __forceinline__ void mma_bf16(float* d, const unsigned* a, const unsigned* b) {
    asm volatile(
        "mma.sync.aligned.m16n8k16.row.col.f32.bf16.bf16.f32 "
        "{%0,%1,%2,%3}, {%4,%5,%6,%7}, {%8,%9}, {%0,%1,%2,%3};"
        : "+f"(d[0]), "+f"(d[1]), "+f"(d[2]), "+f"(d[3])
        : "r"(a[0]), "r"(a[1]), "r"(a[2]), "r"(a[3]), "r"(b[0]), "r"(b[1]));
}

// ============================ LayerNorm =====================================
__global__ __launch_bounds__(256) void ln_kernel(
    const float* __restrict__ x,
    const float* __restrict__ gamma,
    const float* __restrict__ beta)
{
    int row = blockIdx.x;
    const float* xr = x + (size_t)row * HB;
    int tid = threadIdx.x;

    float4 v = *(const float4*)(xr + tid * 4);
    float s  = v.x + v.y + v.z + v.w;
    float ss = v.x*v.x + v.y*v.y + v.z*v.z + v.w*v.w;

    #pragma unroll
    for (int o = 16; o; o >>= 1) {
        s  += __shfl_xor_sync(0xffffffffu, s,  o);
        ss += __shfl_xor_sync(0xffffffffu, ss, o);
    }
    __shared__ float sh_s[8], sh_ss[8];
    int wid = tid >> 5, lid = tid & 31;
    if (lid == 0) { sh_s[wid] = s; sh_ss[wid] = ss; }
    __syncthreads();
    if (wid == 0) {
        float a = (lid < 8) ? sh_s[lid]  : 0.f;
        float b = (lid < 8) ? sh_ss[lid] : 0.f;
        #pragma unroll
        for (int o = 4; o; o >>= 1) {
            a += __shfl_xor_sync(0xffffffffu, a, o);
            b += __shfl_xor_sync(0xffffffffu, b, o);
        }
        if (lid == 0) { sh_s[0] = a; sh_ss[0] = b; }
    }
    __syncthreads();
    float mean = sh_s[0] * (1.0f / HB);
    float var  = sh_ss[0] * (1.0f / HB) - mean * mean;
    float rstd = rsqrtf(var + EPS);

    float4 g  = *(const float4*)(gamma + tid * 4);
    float4 be = *(const float4*)(beta + tid * 4);
    float4 o;
    o.x = (v.x - mean) * rstd * g.x + be.x;
    o.y = (v.y - mean) * rstd * g.y + be.y;
    o.z = (v.z - mean) * rstd * g.z + be.z;
    o.w = (v.w - mean) * rstd * g.w + be.w;
    *(float4*)(g_xn + (size_t)row * HB + tid * 4) = o;
}

// ====================== split-bf16 GEMM core (3-mma / k16) ==================
// C[128,128] per block, BK=16. 256 threads = 8 warps, warp tile 64x32.
// Planes: [k2][row] u32 = packed bf16x2 (adjacent k pair), stride 136
// (136 mod 32 = 8 -> fragment loads conflict-free: bank = 8*q + t4).
#define PL_S 136

#define GEMM_SPLIT_MAINLOOP(Aptr, Bptr)                                       \
    for (int k0 = 0; k0 < HB; k0 += 16) {                                     \
        {                                                                     \
            float4 a0v = *(const float4*)(Aptr + k0 + k8);                    \
            float4 a1v = *(const float4*)(Aptr + k0 + k8 + 4);                \
            float4 b0v = *(const float4*)(Bptr + k0 + k8);                    \
            float4 b1v = *(const float4*)(Bptr + k0 + k8 + 4);                \
            float h0,l0,h1,l1,h2,l2,h3,l3,h4,l4,h5,l5,h6,l6,h7,l7;            \
            split1(a0v.x,h0,l0); split1(a0v.y,h1,l1);                         \
            split1(a0v.z,h2,l2); split1(a0v.w,h3,l3);                         \
            split1(a1v.x,h4,l4); split1(a1v.y,h5,l5);                         \
            split1(a1v.z,h6,l6); split1(a1v.w,h7,l7);                         \
            Ah[(w0+0)*PL_S+aRow]=pack2(h0,h1); Ah[(w0+1)*PL_S+aRow]=pack2(h2,h3);\
            Ah[(w0+2)*PL_S+aRow]=pack2(h4,h5); Ah[(w0+3)*PL_S+aRow]=pack2(h6,h7);\
            Al[(w0+0)*PL_S+aRow]=pack2(l0,l1); Al[(w0+1)*PL_S+aRow]=pack2(l2,l3);\
            Al[(w0+2)*PL_S+aRow]=pack2(l4,l5); Al[(w0+3)*PL_S+aRow]=pack2(l6,l7);\
            split1(b0v.x,h0,l0); split1(b0v.y,h1,l1);                         \
            split1(b0v.z,h2,l2); split1(b0v.w,h3,l3);                         \
            split1(b1v.x,h4,l4); split1(b1v.y,h5,l5);                         \
            split1(b1v.z,h6,l6); split1(b1v.w,h7,l7);                         \
            Bh[(w0+0)*PL_S+aRow]=pack2(h0,h1); Bh[(w0+1)*PL_S+aRow]=pack2(h2,h3);\
            Bh[(w0+2)*PL_S+aRow]=pack2(h4,h5); Bh[(w0+3)*PL_S+aRow]=pack2(h6,h7);\
            Bl[(w0+0)*PL_S+aRow]=pack2(l0,l1); Bl[(w0+1)*PL_S+aRow]=pack2(l2,l3);\
            Bl[(w0+2)*PL_S+aRow]=pack2(l4,l5); Bl[(w0+3)*PL_S+aRow]=pack2(l6,l7);\
        }                                                                     \
        __syncthreads();                                                      \
        {                                                                     \
            unsigned ah[4][4], al[4][4], bh[4][2], bl[4][2];                  \
            _Pragma("unroll")                                                 \
            for (int mt = 0; mt < 4; mt++) {                                  \
                int r = wm + mt*16 + t4;                                      \
                ah[mt][0]=Ah[ q   *PL_S + r    ];                             \
                ah[mt][1]=Ah[ q   *PL_S + r + 8];                             \
                ah[mt][2]=Ah[(q+4)*PL_S + r    ];                             \
                ah[mt][3]=Ah[(q+4)*PL_S + r + 8];                             \
                al[mt][0]=Al[ q   *PL_S + r    ];                             \
                al[mt][1]=Al[ q   *PL_S + r + 8];                             \
                al[mt][2]=Al[(q+4)*PL_S + r    ];                             \
                al[mt][3]=Al[(q+4)*PL_S + r + 8];                             \
            }                                                                 \
            _Pragma("unroll")                                                 \
            for (int nt = 0; nt < 4; nt++) {                                  \
                int c = wn + nt*8 + t4;                                       \
                bh[nt][0]=Bh[ q   *PL_S + c];                                 \
                bh[nt][1]=Bh[(q+4)*PL_S + c];                                 \
                bl[nt][0]=Bl[ q   *PL_S + c];                                 \
                bl[nt][1]=Bl[(q+4)*PL_S + c];                                 \
            }                                                                 \
            _Pragma("unroll")                                                 \
            for (int mt = 0; mt < 4; mt++)                                    \
                _Pragma("unroll")                                             \
                for (int nt = 0; nt < 4; nt++) {                              \
                    mma_bf16(acc[mt][nt], ah[mt], bh[nt]);                    \
                    mma_bf16(acc[mt][nt], ah[mt], bl[nt]);                    \
                    mma_bf16(acc[mt][nt], al[mt], bh[nt]);                    \
                }                                                             \
        }                                                                     \
        __syncthreads();                                                      \
    }

// ---- QKV projections: scatter to [B,NH,S,HD] -------------------------------
__global__ __launch_bounds__(256) void qkv_gemm_t(
    const float* __restrict__ wq, const float* __restrict__ bq,
    const float* __restrict__ wk, const float* __restrict__ bk,
    const float* __restrict__ wv, const float* __restrict__ bv)
{
    const float* W; const float* bias; float* O;
    if      (blockIdx.z == 0) { W = wq; bias = bq; O = g_q; }
    else if (blockIdx.z == 1) { W = wk; bias = bk; O = g_k; }
    else                      { W = wv; bias = bv; O = g_v; }

    __shared__ __align__(16) unsigned Ah[8*PL_S], Al[8*PL_S];
    __shared__ __align__(16) unsigned Bh[8*PL_S], Bl[8*PL_S];

    int tid  = threadIdx.x;
    int aRow = tid >> 1;           // 0..127
    int half = tid & 1;
    int k8   = half * 8;           // f32 k offset
    int w0   = half * 4;           // k2-word offset
    int w    = tid >> 5;
    int lane = tid & 31;
    int t4   = lane >> 2;
    int q    = lane & 3;
    int wm   = (w >> 2) * 64;
    int wn   = (w & 3) * 32;

    const float* Aptr = g_xn + (size_t)(blockIdx.y * 128 + aRow) * HB;
    const float* Bptr = W    + (size_t)(blockIdx.x * 128 + aRow) * HB;

    float acc[4][4][4];
    #pragma unroll
    for (int mt = 0; mt < 4; mt++)
        #pragma unroll
        for (int nt = 0; nt < 4; nt++)
            acc[mt][nt][0] = acc[mt][nt][1] = acc[mt][nt][2] = acc[mt][nt][3] = 0.f;

    GEMM_SPLIT_MAINLOOP(Aptr, Bptr);

    // epilogue: + bias, scatter to [B*NH, S, HD]
    #pragma unroll
    for (int nt = 0; nt < 4; nt++) {
        int col = blockIdx.x * 128 + wn + nt*8 + 2*q;
        int h   = col >> 6;
        int d   = col & 63;
        float b0 = bias[col], b1 = bias[col + 1];
        #pragma unroll
        for (int mt = 0; mt < 4; mt++) {
            int m  = blockIdx.y * 128 + wm + mt*16 + t4;
            int b_ = m >> 11;
            int s_ = m & 2047;
            float* dst = O + ((size_t)(b_ * NH + h) * SEQ + s_) * HD + d;
            *(float2*)dst = make_float2(acc[mt][nt][0] + b0, acc[mt][nt][1] + b1);
            float* dst2 = dst + 8 * HD;   // row + 8, same head/batch
            *(float2*)dst2 = make_float2(acc[mt][nt][2] + b0, acc[mt][nt][3] + b1);
        }
    }
}

// ---- Output projection + residual ------------------------------------------
__global__ __launch_bounds__(256) void out_gemm_t(
    const float* __restrict__ wo, const float* __restrict__ bo,
    const float* __restrict__ hs, float* __restrict__ out)
{
    __shared__ __align__(16) unsigned Ah[8*PL_S], Al[8*PL_S];
    __shared__ __align__(16) unsigned Bh[8*PL_S], Bl[8*PL_S];

    int tid  = threadIdx.x;
    int aRow = tid >> 1;
    int half = tid & 1;
    int k8   = half * 8;
    int w0   = half * 4;
    int w    = tid >> 5;
    int lane = tid & 31;
    int t4   = lane >> 2;
    int q    = lane & 3;
    int wm   = (w >> 2) * 64;
    int wn   = (w & 3) * 32;

    const float* Aptr = g_ctx + (size_t)(blockIdx.y * 128 + aRow) * HB;
    const float* Bptr = wo    + (size_t)(blockIdx.x * 128 + aRow) * HB;

    float acc[4][4][4];
    #pragma unroll
    for (int mt = 0; mt < 4; mt++)
        #pragma unroll
        for (int nt = 0; nt < 4; nt++)
            acc[mt][nt][0] = acc[mt][nt][1] = acc[mt][nt][2] = acc[mt][nt][3] = 0.f;

    GEMM_SPLIT_MAINLOOP(Aptr, Bptr);

    #pragma unroll
    for (int nt = 0; nt < 4; nt++) {
        int col = blockIdx.x * 128 + wn + nt*8 + 2*q;
        float b0 = bo[col], b1 = bo[col + 1];
        #pragma unroll
        for (int mt = 0; mt < 4; mt++) {
            int m = blockIdx.y * 128 + wm + mt*16 + t4;
            const float* hr = hs + (size_t)m * HB + col;
            float* dst = out + (size_t)m * HB + col;
            float2 r0 = *(const float2*)hr;
            *(float2*)dst = make_float2(acc[mt][nt][0] + b0 + r0.x,
                                        acc[mt][nt][1] + b1 + r0.y);
            const float* hr2 = hr + 8 * HB;
            float* dst2 = dst + 8 * HB;
            float2 r1 = *(const float2*)hr2;
            *(float2*)dst2 = make_float2(acc[mt][nt][2] + b0 + r1.x,
                                         acc[mt][nt][3] + b1 + r1.y);
        }
    }
}

// ============================ Flash attention (bf16 mma) ====================
// Block: 128 queries, BN=64 keys/iter. 8 warps; warp w owns query rows
// [w*16, w*16+16). Q in registers as bf16x2 A-fragments (4 k16 chunks).
// Softmax quad-local; P D-fragments ARE the PV A-fragments (just repack).
#define KS_S 36   // u32 stride for Ks [64 keys][32 dim-pairs]
#define VS_S 72   // u32 stride for Vs [32 key-pairs][64 dims]

__global__ __launch_bounds__(256) void attn_t(const float* __restrict__ mask)
{
    __shared__ __align__(16) unsigned Ks[64 * KS_S];
    __shared__ __align__(16) unsigned Vs[32 * VS_S];
    __shared__ float Ms[64];

    int tid  = threadIdx.x;
    int w    = tid >> 5;
    int lane = tid & 31;
    int t4   = lane >> 2;       // groupID
    int q    = lane & 3;        // threadID_in_group

    int bh = blockIdx.y;
    int b  = bh >> 4;
    int h  = bh & 15;
    int q0 = blockIdx.x * 128;

    const float* Qb   = g_q + (size_t)bh * SEQ * HD + (size_t)(q0 + w * 16) * HD;
    const float* Kb   = g_k + (size_t)bh * SEQ * HD;
    const float* Vb   = g_v + (size_t)bh * SEQ * HD;
    const float* mrow = mask + (size_t)b * SEQ;

    // Q A-fragments: 4 k16 chunks over HD=64
    unsigned aq[4][4];
    #pragma unroll
    for (int c = 0; c < 4; c++) {
        const float* qA = Qb + (size_t)t4 * HD + c * 16;
        const float* qB = Qb + (size_t)(t4 + 8) * HD + c * 16;
        float2 x0 = *(const float2*)(qA + 2*q);
        float2 x1 = *(const float2*)(qB + 2*q);
        float2 x2 = *(const float2*)(qA + 8 + 2*q);
        float2 x3 = *(const float2*)(qB + 8 + 2*q);
        aq[c][0] = pack2(x0.x, x0.y);
        aq[c][1] = pack2(x1.x, x1.y);
        aq[c][2] = pack2(x2.x, x2.y);
        aq[c][3] = pack2(x3.x, x3.y);
    }

    float mA = -1e30f, mB = -1e30f, lA = 0.f, lB = 0.f;
    float o[8][4];
    #pragma unroll
    for (int nt = 0; nt < 8; nt++)
        o[nt][0] = o[nt][1] = o[nt][2] = o[nt][3] = 0.f;

    for (int kt0 = 0; kt0 < SEQ; kt0 += 64) {
        // ---- stage K [64][64] as dim-pairs; V as key-pairs ----
        for (int idx = tid; idx < 64 * 16; idx += 256) {
            int r  = idx >> 4;
            int c4 = (idx & 15) << 2;
            float4 kv = *(const float4*)(Kb + (size_t)(kt0 + r) * HD + c4);
            Ks[r * KS_S + (c4 >> 1)    ] = pack2(kv.x, kv.y);
            Ks[r * KS_S + (c4 >> 1) + 1] = pack2(kv.z, kv.w);
        }
        for (int idx = tid; idx < 32 * 16; idx += 256) {
            int k2 = idx >> 4;
            int c4 = (idx & 15) << 2;
            float4 v0 = *(const float4*)(Vb + (size_t)(kt0 + 2*k2    ) * HD + c4);
            float4 v1 = *(const float4*)(Vb + (size_t)(kt0 + 2*k2 + 1) * HD + c4);
            Vs[k2 * VS_S + c4 + 0] = pack2(v0.x, v1.x);
            Vs[k2 * VS_S + c4 + 1] = pack2(v0.y, v1.y);
            Vs[k2 * VS_S + c4 + 2] = pack2(v0.z, v1.z);
            Vs[k2 * VS_S + c4 + 3] = pack2(v0.w, v1.w);
        }
        if (tid < 64) Ms[tid] = mrow[kt0 + tid];
        __syncthreads();

        // ---- QK^T: s[nt] covers keys nt*8..nt*8+7 ----
        float s[8][4];
        #pragma unroll
        for (int nt = 0; nt < 8; nt++)
            s[nt][0] = s[nt][1] = s[nt][2] = s[nt][3] = 0.f;

        #pragma unroll
        for (int c = 0; c < 4; c++) {
            #pragma unroll
            for (int nt = 0; nt < 8; nt++) {
                unsigned bb[2];
                bb[0] = Ks[(nt*8 + t4) * KS_S + c*8 + q    ];
                bb[1] = Ks[(nt*8 + t4) * KS_S + c*8 + 4 + q];
                mma_bf16(s[nt], aq[c], bb);
            }
        }

        // ---- scale + mask ----
        #pragma unroll
        for (int nt = 0; nt < 8; nt++) {
            float mk0 = Ms[nt*8 + 2*q];
            float mk1 = Ms[nt*8 + 2*q + 1];
            s[nt][0] = s[nt][0] * 0.125f + mk0;
            s[nt][1] = s[nt][1] * 0.125f + mk1;
            s[nt][2] = s[nt][2] * 0.125f + mk0;
            s[nt][3] = s[nt][3] * 0.125f + mk1;
        }

        // ---- online softmax (rows rA=t4, rB=t4+8; reduce over quad) ----
        float mxA = -1e30f, mxB = -1e30f;
        #pragma unroll
        for (int nt = 0; nt < 8; nt++) {
            mxA = fmaxf(mxA, fmaxf(s[nt][0], s[nt][1]));
            mxB = fmaxf(mxB, fmaxf(s[nt][2], s[nt][3]));
        }
        mxA = fmaxf(mxA, __shfl_xor_sync(0xffffffffu, mxA, 1));
        mxA = fmaxf(mxA, __shfl_xor_sync(0xffffffffu, mxA, 2));
        mxB = fmaxf(mxB, __shfl_xor_sync(0xffffffffu, mxB, 1));
        mxB = fmaxf(mxB, __shfl_xor_sync(0xffffffffu, mxB, 2));
        float mAn = fmaxf(mA, mxA), mBn = fmaxf(mB, mxB);
        float alA = __expf(mA - mAn), alB = __expf(mB - mBn);
        float sumA = 0.f, sumB = 0.f;
        #pragma unroll
        for (int nt = 0; nt < 8; nt++) {
            s[nt][0] = __expf(s[nt][0] - mAn);
            s[nt][1] = __expf(s[nt][1] - mAn);
            s[nt][2] = __expf(s[nt][2] - mBn);
            s[nt][3] = __expf(s[nt][3] - mBn);
            sumA += s[nt][0] + s[nt][1];
            sumB += s[nt][2] + s[nt][3];
        }
        sumA += __shfl_xor_sync(0xffffffffu, sumA, 1);
        sumA += __shfl_xor_sync(0xffffffffu, sumA, 2);
        sumB += __shfl_xor_sync(0xffffffffu, sumB, 1);
        sumB += __shfl_xor_sync(0xffffffffu, sumB, 2);
        lA = lA * alA + sumA;  mA = mAn;
        lB = lB * alB + sumB;  mB = mBn;
        #pragma unroll
        for (int nt = 0; nt < 8; nt++) {
            o[nt][0] *= alA; o[nt][1] *= alA;
            o[nt][2] *= alB; o[nt][3] *= alB;
        }

        // ---- PV: P D-fragments repack directly into A-fragments ----
        #pragma unroll
        for (int pk = 0; pk < 4; pk++) {
            unsigned pa[4];
            pa[0] = pack2(s[2*pk  ][0], s[2*pk  ][1]);
            pa[1] = pack2(s[2*pk  ][2], s[2*pk  ][3]);
            pa[2] = pack2(s[2*pk+1][0], s[2*pk+1][1]);
            pa[3] = pack2(s[2*pk+1][2], s[2*pk+1][3]);
            #pragma unroll
            for (int nt = 0; nt < 8; nt++) {
                unsigned bb[2];
                bb[0] = Vs[(pk*8 + q    ) * VS_S + nt*8 + t4];
                bb[1] = Vs[(pk*8 + q + 4) * VS_S + nt*8 + t4];
                mma_bf16(o[nt], pa, bb);
            }
        }
        __syncthreads();
    }

    // ---- epilogue -> g_ctx [B,S,H] ----
    float invA = 1.0f / lA, invB = 1.0f / lB;
    int srowA = q0 + w * 16 + t4;
    #pragma unroll
    for (int nt = 0; nt < 8; nt++) {
        int d = h * HD + nt * 8 + 2 * q;
        float* dst = g_ctx + ((size_t)(b * SEQ + srowA) * HB) + d;
        *(float2*)dst = make_float2(o[nt][0] * invA, o[nt][1] * invA);
        float* dst2 = g_ctx + ((size_t)(b * SEQ + srowA + 8) * HB) + d;
        *(float2*)dst2 = make_float2(o[nt][2] * invB, o[nt][3] * invB);
    }
}

// ============================ launch ========================================
extern "C" void kernel_launch(void* const* d_in, const int* in_sizes, int n_in,
                              void* d_out, int out_size)
{
    const float* hs    = (const float*)d_in[0];
    const float* mask  = (const float*)d_in[1];
    const float* wq    = (const float*)d_in[2];
    const float* bq    = (const float*)d_in[3];
    const float* wk    = (const float*)d_in[4];
    const float* bk    = (const float*)d_in[5];
    const float* wv    = (const float*)d_in[6];
    const float* bv    = (const float*)d_in[7];
    const float* wo    = (const float*)d_in[8];
    const float* bo    = (const float*)d_in[9];
    const float* gamma = (const float*)d_in[10];
    const float* beta  = (const float*)d_in[11];
    float* out = (float*)d_out;

    ln_kernel<<<ROWS, 256>>>(hs, gamma, beta);
    qkv_gemm_t<<<dim3(HB/128, ROWS/128, 3), 256>>>(wq, bq, wk, bk, wv, bv);
    attn_t<<<dim3(SEQ/128, BATCH*NH), 256>>>(mask);
    out_gemm_t<<<dim3(HB/128, ROWS/128), 256>>>(wo, bo, hs, out);
}

// round 11
// speedup vs baseline: 3.6150x; 1.2852x over previous
#include <cuda_runtime.h>
#include <cuda_bf16.h>

// Problem dims
#define HB    1024
#define NH    16
#define HD    64
#define SEQ   2048
#define BATCH 2
#define ROWS  (BATCH*SEQ)     // 4096
#define EPS   1e-12f
#define W2    (HB/2)          // 512 packed u32 per hidden row

// -------------------- scratch (device globals; no runtime allocs) -----------
// All intermediates stored as packed bf16x2 (u32 = pair along k / hidden dim).
__device__ unsigned g_xnb [ROWS*W2];     // layernorm output, bf16 packed
__device__ unsigned g_wb  [4*HB*W2];     // wq,wk,wv,wo bf16 packed [mat][n][k2]
__device__ unsigned g_qb  [ROWS*W2];     // [B,NH,S,HD/2]
__device__ unsigned g_kb  [ROWS*W2];
__device__ unsigned g_vb  [ROWS*W2];
__device__ unsigned g_ctxb[ROWS*W2];     // [B,S,H/2]

// -------------------- bf16 helpers ------------------------------------------
__device__ __forceinline__ unsigned pack2(float a, float b) {
    unsigned r;
    asm("{ .reg .b16 lo, hi;\n\t"
        "cvt.rn.bf16.f32 lo, %1;\n\t"
        "cvt.rn.bf16.f32 hi, %2;\n\t"
        "mov.b32 %0, {lo, hi}; }"
        : "=r"(r) : "f"(a), "f"(b));
    return r;
}
// D += A(16x16) * B(16x8), bf16 in, f32 accum.
__device__ __forceinline__ void mma_bf16(float* d, const unsigned* a, const unsigned* b) {
    asm volatile(
        "mma.sync.aligned.m16n8k16.row.col.f32.bf16.bf16.f32 "
        "{%0,%1,%2,%3}, {%4,%5,%6,%7}, {%8,%9}, {%0,%1,%2,%3};"
        : "+f"(d[0]), "+f"(d[1]), "+f"(d[2]), "+f"(d[3])
        : "r"(a[0]), "r"(a[1]), "r"(a[2]), "r"(a[3]), "r"(b[0]), "r"(b[1]));
}

// ============================ LayerNorm (writes bf16 planes) ================
__global__ __launch_bounds__(256) void ln_kernel(
    const float* __restrict__ x,
    const float* __restrict__ gamma,
    const float* __restrict__ beta)
{
    int row = blockIdx.x;
    const float* xr = x + (size_t)row * HB;
    int tid = threadIdx.x;

    float4 v = *(const float4*)(xr + tid * 4);
    float s  = v.x + v.y + v.z + v.w;
    float ss = v.x*v.x + v.y*v.y + v.z*v.z + v.w*v.w;

    #pragma unroll
    for (int o = 16; o; o >>= 1) {
        s  += __shfl_xor_sync(0xffffffffu, s,  o);
        ss += __shfl_xor_sync(0xffffffffu, ss, o);
    }
    __shared__ float sh_s[8], sh_ss[8];
    int wid = tid >> 5, lid = tid & 31;
    if (lid == 0) { sh_s[wid] = s; sh_ss[wid] = ss; }
    __syncthreads();
    if (wid == 0) {
        float a = (lid < 8) ? sh_s[lid]  : 0.f;
        float b = (lid < 8) ? sh_ss[lid] : 0.f;
        #pragma unroll
        for (int o = 4; o; o >>= 1) {
            a += __shfl_xor_sync(0xffffffffu, a, o);
            b += __shfl_xor_sync(0xffffffffu, b, o);
        }
        if (lid == 0) { sh_s[0] = a; sh_ss[0] = b; }
    }
    __syncthreads();
    float mean = sh_s[0] * (1.0f / HB);
    float var  = sh_ss[0] * (1.0f / HB) - mean * mean;
    float rstd = rsqrtf(var + EPS);

    float4 g  = *(const float4*)(gamma + tid * 4);
    float4 be = *(const float4*)(beta + tid * 4);
    float o0 = (v.x - mean) * rstd * g.x + be.x;
    float o1 = (v.y - mean) * rstd * g.y + be.y;
    float o2 = (v.z - mean) * rstd * g.z + be.z;
    float o3 = (v.w - mean) * rstd * g.w + be.w;
    *(uint2*)(g_xnb + (size_t)row * W2 + tid * 2) =
        make_uint2(pack2(o0, o1), pack2(o2, o3));
}

// ============================ Weight conversion =============================
__global__ __launch_bounds__(256) void conv_w(
    const float* __restrict__ wq, const float* __restrict__ wk,
    const float* __restrict__ wv, const float* __restrict__ wo)
{
    int gid = blockIdx.x * 256 + threadIdx.x;    // 4 * HB*HB/4 threads
    int mat = gid >> 18;                          // HB*HB/4 = 262144
    int off = gid & 262143;
    const float* src = (mat == 0 ? wq : mat == 1 ? wk : mat == 2 ? wv : wo)
                       + (size_t)off * 4;
    float4 v = *(const float4*)src;
    *(uint2*)(g_wb + (size_t)mat * HB * W2 + (size_t)off * 2) =
        make_uint2(pack2(v.x, v.y), pack2(v.z, v.w));
}

// ====================== bf16 GEMM mainloop (double-buffered) ================
// C[128,128] per block, BK=32. 256 threads = 8 warps, warp tile 64x32.
// Smem planes [k2][row], stride PL_S=136 (mod 32 = 8 -> conflict-free frags).
// Warps 0-3 stage A rows, warps 4-7 stage B rows (conflict-free STS).
#define PL_S  136
#define STG   (16*PL_S)      // one plane, one stage (16 k-pairs)
#define STAGE2 (2*STG)       // A+B planes, one stage

__device__ __forceinline__ void gemm_mainloop(
    const unsigned* __restrict__ Ag,   // bf16 plane, + by*128 rows
    const unsigned* __restrict__ Bg,   // bf16 plane, + bx*128 rows
    unsigned* Sh,                      // [2][2][16*PL_S]
    float (*acc)[4][4])
{
    int tid  = threadIdx.x;
    int side = tid >> 7;               // 0 = A loader, 1 = B loader
    int row  = tid & 127;
    int lane = tid & 31, w = tid >> 5;
    int t4 = lane >> 2, q = lane & 3;
    int wm = (w >> 2) * 64, wn = (w & 3) * 32;

    const unsigned* grow = (side ? Bg : Ag) + (size_t)row * W2;

    uint4 r0 = *(const uint4*)(grow     );
    uint4 r1 = *(const uint4*)(grow +  4);
    uint4 r2 = *(const uint4*)(grow +  8);
    uint4 r3 = *(const uint4*)(grow + 12);
    {
        unsigned* stb = Sh + side * STG + row;
        stb[ 0*PL_S]=r0.x; stb[ 1*PL_S]=r0.y; stb[ 2*PL_S]=r0.z; stb[ 3*PL_S]=r0.w;
        stb[ 4*PL_S]=r1.x; stb[ 5*PL_S]=r1.y; stb[ 6*PL_S]=r1.z; stb[ 7*PL_S]=r1.w;
        stb[ 8*PL_S]=r2.x; stb[ 9*PL_S]=r2.y; stb[10*PL_S]=r2.z; stb[11*PL_S]=r2.w;
        stb[12*PL_S]=r3.x; stb[13*PL_S]=r3.y; stb[14*PL_S]=r3.z; stb[15*PL_S]=r3.w;
    }
    __syncthreads();

    int cur = 0;
    for (int k0 = 32; k0 <= HB; k0 += 32) {
        if (k0 < HB) {
            const unsigned* g2 = grow + (k0 >> 1);
            r0 = *(const uint4*)(g2     );
            r1 = *(const uint4*)(g2 +  4);
            r2 = *(const uint4*)(g2 +  8);
            r3 = *(const uint4*)(g2 + 12);
        }
        const unsigned* Ahs = Sh + cur * STAGE2;
        const unsigned* Bhs = Ahs + STG;
        #pragma unroll
        for (int s = 0; s < 2; s++) {
            int kb = s * 8;
            unsigned ah[4][4], bh[4][2];
            #pragma unroll
            for (int mt = 0; mt < 4; mt++) {
                int r = wm + mt*16 + t4;
                ah[mt][0] = Ahs[(kb+q  )*PL_S + r    ];
                ah[mt][1] = Ahs[(kb+q  )*PL_S + r + 8];
                ah[mt][2] = Ahs[(kb+q+4)*PL_S + r    ];
                ah[mt][3] = Ahs[(kb+q+4)*PL_S + r + 8];
            }
            #pragma unroll
            for (int nt = 0; nt < 4; nt++) {
                int c = wn + nt*8 + t4;
                bh[nt][0] = Bhs[(kb+q  )*PL_S + c];
                bh[nt][1] = Bhs[(kb+q+4)*PL_S + c];
            }
            #pragma unroll
            for (int mt = 0; mt < 4; mt++)
                #pragma unroll
                for (int nt = 0; nt < 4; nt++)
                    mma_bf16(acc[mt][nt], ah[mt], bh[nt]);
        }
        if (k0 < HB) {
            unsigned* stb = Sh + (cur^1) * STAGE2 + side * STG + row;
            stb[ 0*PL_S]=r0.x; stb[ 1*PL_S]=r0.y; stb[ 2*PL_S]=r0.z; stb[ 3*PL_S]=r0.w;
            stb[ 4*PL_S]=r1.x; stb[ 5*PL_S]=r1.y; stb[ 6*PL_S]=r1.z; stb[ 7*PL_S]=r1.w;
            stb[ 8*PL_S]=r2.x; stb[ 9*PL_S]=r2.y; stb[10*PL_S]=r2.z; stb[11*PL_S]=r2.w;
            stb[12*PL_S]=r3.x; stb[13*PL_S]=r3.y; stb[14*PL_S]=r3.z; stb[15*PL_S]=r3.w;
        }
        __syncthreads();
        cur ^= 1;
    }
}

// ---- QKV projections: write packed bf16, scattered to [B,NH,S,HD/2] --------
__global__ __launch_bounds__(256) void qkv_gemm_t(
    const float* __restrict__ bq, const float* __restrict__ bk,
    const float* __restrict__ bv)
{
    int z = blockIdx.z;
    const float* bias = (z == 0) ? bq : (z == 1) ? bk : bv;
    unsigned* O = (z == 0) ? g_qb : (z == 1) ? g_kb : g_vb;

    __shared__ __align__(16) unsigned Sh[2*STAGE2];

    const unsigned* Ag = g_xnb + (size_t)(blockIdx.y * 128) * W2;
    const unsigned* Bg = g_wb + (size_t)z * HB * W2 + (size_t)(blockIdx.x * 128) * W2;

    float acc[4][4][4];
    #pragma unroll
    for (int mt = 0; mt < 4; mt++)
        #pragma unroll
        for (int nt = 0; nt < 4; nt++)
            acc[mt][nt][0] = acc[mt][nt][1] = acc[mt][nt][2] = acc[mt][nt][3] = 0.f;

    gemm_mainloop(Ag, Bg, Sh, acc);

    int tid = threadIdx.x;
    int lane = tid & 31, w = tid >> 5;
    int t4 = lane >> 2, q = lane & 3;
    int wm = (w >> 2) * 64, wn = (w & 3) * 32;

    #pragma unroll
    for (int nt = 0; nt < 4; nt++) {
        int col = blockIdx.x * 128 + wn + nt*8 + 2*q;
        int h   = col >> 6;
        int dp  = (col & 63) >> 1;
        float b0 = bias[col], b1 = bias[col + 1];
        #pragma unroll
        for (int mt = 0; mt < 4; mt++) {
            int m  = blockIdx.y * 128 + wm + mt*16 + t4;
            int b_ = m >> 11;
            int s_ = m & 2047;
            unsigned* dst = O + ((size_t)(b_ * NH + h) * SEQ + s_) * (HD/2) + dp;
            dst[0]          = pack2(acc[mt][nt][0] + b0, acc[mt][nt][1] + b1);
            dst[8 * (HD/2)] = pack2(acc[mt][nt][2] + b0, acc[mt][nt][3] + b1);
        }
    }
}

// ---- Output projection + residual (f32 out) --------------------------------
__global__ __launch_bounds__(256) void out_gemm_t(
    const float* __restrict__ bo,
    const float* __restrict__ hs, float* __restrict__ out)
{
    __shared__ __align__(16) unsigned Sh[2*STAGE2];

    const unsigned* Ag = g_ctxb + (size_t)(blockIdx.y * 128) * W2;
    const unsigned* Bg = g_wb + (size_t)3 * HB * W2 + (size_t)(blockIdx.x * 128) * W2;

    float acc[4][4][4];
    #pragma unroll
    for (int mt = 0; mt < 4; mt++)
        #pragma unroll
        for (int nt = 0; nt < 4; nt++)
            acc[mt][nt][0] = acc[mt][nt][1] = acc[mt][nt][2] = acc[mt][nt][3] = 0.f;

    gemm_mainloop(Ag, Bg, Sh, acc);

    int tid = threadIdx.x;
    int lane = tid & 31, w = tid >> 5;
    int t4 = lane >> 2, q = lane & 3;
    int wm = (w >> 2) * 64, wn = (w & 3) * 32;

    #pragma unroll
    for (int nt = 0; nt < 4; nt++) {
        int col = blockIdx.x * 128 + wn + nt*8 + 2*q;
        float b0 = bo[col], b1 = bo[col + 1];
        #pragma unroll
        for (int mt = 0; mt < 4; mt++) {
            int m = blockIdx.y * 128 + wm + mt*16 + t4;
            const float* hr = hs + (size_t)m * HB + col;
            float* dst = out + (size_t)m * HB + col;
            float2 r0 = *(const float2*)hr;
            *(float2*)dst = make_float2(acc[mt][nt][0] + b0 + r0.x,
                                        acc[mt][nt][1] + b1 + r0.y);
            const float* hr2 = hr + 8 * HB;
            float* dst2 = dst + 8 * HB;
            float2 r1 = *(const float2*)hr2;
            *(float2*)dst2 = make_float2(acc[mt][nt][2] + b0 + r1.x,
                                         acc[mt][nt][3] + b1 + r1.y);
        }
    }
}

// ============================ Flash attention (bf16, double-buffered) =======
// 128 queries/block, BN=64 keys/iter. 8 warps; warp w: query rows [w*16,w*16+16).
// Q/K/V already bf16-packed in gmem -> staging is pure u32 copy (+prmt for V).
#define KS_S 36   // u32 stride, Ks rows = keys, cols = dim-pairs
#define VS_S 72   // u32 stride, Vs rows = key-pairs, cols = dims

__global__ __launch_bounds__(256) void attn_t(const float* __restrict__ mask)
{
    __shared__ __align__(16) unsigned Ks[2][64 * KS_S];
    __shared__ __align__(16) unsigned Vs[2][32 * VS_S];
    __shared__ float Ms[2][64];

    int tid  = threadIdx.x;
    int w    = tid >> 5;
    int lane = tid & 31;
    int t4   = lane >> 2;
    int q    = lane & 3;

    int bh = blockIdx.y;
    int b  = bh >> 4;
    int h  = bh & 15;
    int q0 = blockIdx.x * 128;

    const unsigned* Qp = g_qb + (size_t)bh * SEQ * (HD/2) + (size_t)(q0 + w * 16) * (HD/2);
    const unsigned* Kp = g_kb + (size_t)bh * SEQ * (HD/2);
    const unsigned* Vp = g_vb + (size_t)bh * SEQ * (HD/2);
    const float* mrow  = mask + (size_t)b * SEQ;

    // Q A-fragments: direct u32 loads (already packed dim-pairs)
    unsigned aq[4][4];
    #pragma unroll
    for (int c = 0; c < 4; c++) {
        aq[c][0] = Qp[(size_t)(t4    ) * (HD/2) + c*8 + q    ];
        aq[c][1] = Qp[(size_t)(t4 + 8) * (HD/2) + c*8 + q    ];
        aq[c][2] = Qp[(size_t)(t4    ) * (HD/2) + c*8 + q + 4];
        aq[c][3] = Qp[(size_t)(t4 + 8) * (HD/2) + c*8 + q + 4];
    }

    // staging assignments
    int kr = tid & 63, kc = tid >> 6;     // K: key row, dim-chunk (0..3)
    int vk = tid >> 3, vj = tid & 7;      // V: key-pair (0..31), dim-chunk (0..7)

    uint4 ka, kb2, va, vb2;
    float mreg = 0.f;

    auto LOADT = [&](int kt0) {
        ka  = *(const uint4*)(Kp + (size_t)(kt0 + kr) * 32 + 4*kc);
        kb2 = *(const uint4*)(Kp + (size_t)(kt0 + kr) * 32 + 4*kc + 16);
        va  = *(const uint4*)(Vp + (size_t)(kt0 + 2*vk    ) * 32 + 4*vj);
        vb2 = *(const uint4*)(Vp + (size_t)(kt0 + 2*vk + 1) * 32 + 4*vj);
        if (tid < 64) mreg = mrow[kt0 + tid];
    };
    auto STORET = [&](int st) {
        *(uint4*)&Ks[st][kr * KS_S + 4*kc     ] = ka;
        *(uint4*)&Ks[st][kr * KS_S + 4*kc + 16] = kb2;
        uint4 o0, o1;
        o0.x = __byte_perm(va.x, vb2.x, 0x5410);
        o0.y = __byte_perm(va.x, vb2.x, 0x7632);
        o0.z = __byte_perm(va.y, vb2.y, 0x5410);
        o0.w = __byte_perm(va.y, vb2.y, 0x7632);
        o1.x = __byte_perm(va.z, vb2.z, 0x5410);
        o1.y = __byte_perm(va.z, vb2.z, 0x7632);
        o1.z = __byte_perm(va.w, vb2.w, 0x5410);
        o1.w = __byte_perm(va.w, vb2.w, 0x7632);
        *(uint4*)&Vs[st][vk * VS_S + 8*vj    ] = o0;
        *(uint4*)&Vs[st][vk * VS_S + 8*vj + 4] = o1;
        if (tid < 64) Ms[st][tid] = mreg;
    };

    float mA = -1e30f, mB = -1e30f, lA = 0.f, lB = 0.f;
    float o[8][4];
    #pragma unroll
    for (int nt = 0; nt < 8; nt++)
        o[nt][0] = o[nt][1] = o[nt][2] = o[nt][3] = 0.f;

    LOADT(0);
    STORET(0);
    __syncthreads();

    int cur = 0;
    for (int t = 0; t < SEQ/64; t++) {
        if (t + 1 < SEQ/64) LOADT((t + 1) * 64);

        const unsigned* Kss = Ks[cur];
        const unsigned* Vss = Vs[cur];
        const float*    Mss = Ms[cur];

        // ---- QK^T ----
        float s[8][4];
        #pragma unroll
        for (int nt = 0; nt < 8; nt++)
            s[nt][0] = s[nt][1] = s[nt][2] = s[nt][3] = 0.f;

        #pragma unroll
        for (int c = 0; c < 4; c++) {
            #pragma unroll
            for (int nt = 0; nt < 8; nt++) {
                unsigned bb[2];
                bb[0] = Kss[(nt*8 + t4) * KS_S + c*8 + q    ];
                bb[1] = Kss[(nt*8 + t4) * KS_S + c*8 + 4 + q];
                mma_bf16(s[nt], aq[c], bb);
            }
        }

        // ---- scale + mask ----
        #pragma unroll
        for (int nt = 0; nt < 8; nt++) {
            float mk0 = Mss[nt*8 + 2*q];
            float mk1 = Mss[nt*8 + 2*q + 1];
            s[nt][0] = s[nt][0] * 0.125f + mk0;
            s[nt][1] = s[nt][1] * 0.125f + mk1;
            s[nt][2] = s[nt][2] * 0.125f + mk0;
            s[nt][3] = s[nt][3] * 0.125f + mk1;
        }

        // ---- online softmax (rows rA=t4, rB=t4+8; quad reduce) ----
        float mxA = -1e30f, mxB = -1e30f;
        #pragma unroll
        for (int nt = 0; nt < 8; nt++) {
            mxA = fmaxf(mxA, fmaxf(s[nt][0], s[nt][1]));
            mxB = fmaxf(mxB, fmaxf(s[nt][2], s[nt][3]));
        }
        mxA = fmaxf(mxA, __shfl_xor_sync(0xffffffffu, mxA, 1));
        mxA = fmaxf(mxA, __shfl_xor_sync(0xffffffffu, mxA, 2));
        mxB = fmaxf(mxB, __shfl_xor_sync(0xffffffffu, mxB, 1));
        mxB = fmaxf(mxB, __shfl_xor_sync(0xffffffffu, mxB, 2));
        float mAn = fmaxf(mA, mxA), mBn = fmaxf(mB, mxB);
        float alA = __expf(mA - mAn), alB = __expf(mB - mBn);
        float sumA = 0.f, sumB = 0.f;
        #pragma unroll
        for (int nt = 0; nt < 8; nt++) {
            s[nt][0] = __expf(s[nt][0] - mAn);
            s[nt][1] = __expf(s[nt][1] - mAn);
            s[nt][2] = __expf(s[nt][2] - mBn);
            s[nt][3] = __expf(s[nt][3] - mBn);
            sumA += s[nt][0] + s[nt][1];
            sumB += s[nt][2] + s[nt][3];
        }
        sumA += __shfl_xor_sync(0xffffffffu, sumA, 1);
        sumA += __shfl_xor_sync(0xffffffffu, sumA, 2);
        sumB += __shfl_xor_sync(0xffffffffu, sumB, 1);
        sumB += __shfl_xor_sync(0xffffffffu, sumB, 2);
        lA = lA * alA + sumA;  mA = mAn;
        lB = lB * alB + sumB;  mB = mBn;
        #pragma unroll
        for (int nt = 0; nt < 8; nt++) {
            o[nt][0] *= alA; o[nt][1] *= alA;
            o[nt][2] *= alB; o[nt][3] *= alB;
        }

        // ---- PV: P D-fragments repack directly into A-fragments ----
        #pragma unroll
        for (int pk = 0; pk < 4; pk++) {
            unsigned pa[4];
            pa[0] = pack2(s[2*pk  ][0], s[2*pk  ][1]);
            pa[1] = pack2(s[2*pk  ][2], s[2*pk  ][3]);
            pa[2] = pack2(s[2*pk+1][0], s[2*pk+1][1]);
            pa[3] = pack2(s[2*pk+1][2], s[2*pk+1][3]);
            #pragma unroll
            for (int nt = 0; nt < 8; nt++) {
                unsigned bb[2];
                bb[0] = Vss[(pk*8 + q    ) * VS_S + nt*8 + t4];
                bb[1] = Vss[(pk*8 + q + 4) * VS_S + nt*8 + t4];
                mma_bf16(o[nt], pa, bb);
            }
        }

        if (t + 1 < SEQ/64) STORET(cur ^ 1);
        __syncthreads();
        cur ^= 1;
    }

    // ---- epilogue -> g_ctxb packed [B,S,H/2] ----
    float invA = 1.0f / lA, invB = 1.0f / lB;
    int srowA = q0 + w * 16 + t4;
    unsigned* crow  = g_ctxb + (size_t)(b * SEQ + srowA    ) * W2 + h * 32;
    unsigned* crow2 = g_ctxb + (size_t)(b * SEQ + srowA + 8) * W2 + h * 32;
    #pragma unroll
    for (int nt = 0; nt < 8; nt++) {
        crow [nt*4 + q] = pack2(o[nt][0] * invA, o[nt][1] * invA);
        crow2[nt*4 + q] = pack2(o[nt][2] * invB, o[nt][3] * invB);
    }
}

// ============================ launch ========================================
extern "C" void kernel_launch(void* const* d_in, const int* in_sizes, int n_in,
                              void* d_out, int out_size)
{
    const float* hs    = (const float*)d_in[0];
    const float* mask  = (const float*)d_in[1];
    const float* wq    = (const float*)d_in[2];
    const float* bq    = (const float*)d_in[3];
    const float* wk    = (const float*)d_in[4];
    const float* bk    = (const float*)d_in[5];
    const float* wv    = (const float*)d_in[6];
    const float* bv    = (const float*)d_in[7];
    const float* wo    = (const float*)d_in[8];
    const float* bo    = (const float*)d_in[9];
    const float* gamma = (const float*)d_in[10];
    const float* beta  = (const float*)d_in[11];
    float* out = (float*)d_out;

    conv_w<<<4096, 256>>>(wq, wk, wv, wo);
    ln_kernel<<<ROWS, 256>>>(hs, gamma, beta);
    qkv_gemm_t<<<dim3(HB/128, ROWS/128, 3), 256>>>(bq, bk, bv);
    attn_t<<<dim3(SEQ/128, BATCH*NH), 256>>>(mask);
    out_gemm_t<<<dim3(HB/128, ROWS/128), 256>>>(bo, hs, out);
}